// round 2
// baseline (speedup 1.0000x reference)
#include <cuda_runtime.h>
#include <cstdint>

// Problem constants
#define BB 8192
#define DD 300
#define HH 512
#define WW 8

// ---------------- scratch (no allocations allowed) ----------------
// x projections: ii, ig, io, lx  -> 4 chunks of [B,H]
__device__ float g_xw[(size_t)4 * BB * HH];
// h0 projections: hi, hg, ho     -> 3 chunks of [B,H]
__device__ float g_hw[(size_t)3 * BB * HH];
// edge GEMM: all_c_b_e_w @ w_lc + b_lc -> [B*W, H]
__device__ float g_edge[(size_t)BB * WW * HH];

// ---------------- generic multi-set SGEMM ----------------
// C_z[M,512] = A[M,K] @ W_z[K,512] + bias_z ; z = blockIdx.z selects weight set.
struct Sets4 {
    const float* W[4];
    const float* bias[4];
    float*       C[4];
};

#define BM 128
#define BN 128
#define BK 8

__global__ void __launch_bounds__(256)
sgemm_multi(const float* __restrict__ A, int M, int K, Sets4 sets)
{
    const int z = blockIdx.z;
    const float* __restrict__ W    = sets.W[z];
    const float* __restrict__ bias = sets.bias[z];
    float* __restrict__       C    = sets.C[z];

    const int row0 = blockIdx.y * BM;
    const int col0 = blockIdx.x * BN;

    __shared__ float As[BK][BM + 4];   // +4 pad: conflict-free transposed store
    __shared__ float Bs[BK][BN];

    float acc[8][8];
#pragma unroll
    for (int i = 0; i < 8; i++)
#pragma unroll
        for (int j = 0; j < 8; j++) acc[i][j] = 0.f;

    const int t  = threadIdx.x;
    const int ty = t >> 4;       // 0..15
    const int tx = t & 15;       // 0..15

    for (int k0 = 0; k0 < K; k0 += BK) {
        // load A tile 128x8 (transposed into As[k][m]); 8 consecutive k per
        // 8-thread group = one 32B sector
#pragma unroll
        for (int i = 0; i < 4; i++) {
            int idx = t + i * 256;
            int kk = idx & 7;
            int mm = idx >> 3;
            int gk = k0 + kk;
            As[kk][mm] = (gk < K) ? A[(size_t)(row0 + mm) * K + gk] : 0.f;
        }
        // load B tile 8x128, fully coalesced
#pragma unroll
        for (int i = 0; i < 4; i++) {
            int idx = t + i * 256;
            int kk = idx >> 7;
            int nn = idx & 127;
            int gk = k0 + kk;
            Bs[kk][nn] = (gk < K) ? W[(size_t)gk * HH + col0 + nn] : 0.f;
        }
        __syncthreads();

#pragma unroll
        for (int kk = 0; kk < BK; kk++) {
            float a[8], b[8];
#pragma unroll
            for (int i = 0; i < 8; i++) a[i] = As[kk][ty * 8 + i];
#pragma unroll
            for (int j = 0; j < 8; j++) b[j] = Bs[kk][tx * 8 + j];
#pragma unroll
            for (int i = 0; i < 8; i++)
#pragma unroll
                for (int j = 0; j < 8; j++) acc[i][j] += a[i] * b[j];
        }
        __syncthreads();
    }

    // epilogue: + bias, vectorized float4 stores (col0 + tx*8 is 32B-aligned)
#pragma unroll
    for (int i = 0; i < 8; i++) {
        size_t r = (size_t)(row0 + ty * 8 + i) * HH + col0 + tx * 8;
        float4 v0, v1;
        v0.x = acc[i][0] + bias[col0 + tx * 8 + 0];
        v0.y = acc[i][1] + bias[col0 + tx * 8 + 1];
        v0.z = acc[i][2] + bias[col0 + tx * 8 + 2];
        v0.w = acc[i][3] + bias[col0 + tx * 8 + 3];
        v1.x = acc[i][4] + bias[col0 + tx * 8 + 4];
        v1.y = acc[i][5] + bias[col0 + tx * 8 + 5];
        v1.z = acc[i][6] + bias[col0 + tx * 8 + 6];
        v1.w = acc[i][7] + bias[col0 + tx * 8 + 7];
        *reinterpret_cast<float4*>(&C[r])     = v0;
        *reinterpret_cast<float4*>(&C[r + 4]) = v1;
    }
}

// ---------------- fused lattice-LSTM epilogue ----------------
__global__ void __launch_bounds__(256)
lattice_epilogue(const float* __restrict__ xw,   // 4 chunks: ii, ig, io, lx
                 const float* __restrict__ hw,   // 3 chunks: hi, hg, ho
                 const float* __restrict__ edge, // [B*W,H], incl. b_lc
                 const float* __restrict__ allc, // [B,W,H]
                 const int*   __restrict__ numw, // [B]
                 float* __restrict__ out)        // [2*B*H] = h1 then c
{
    const size_t CH = (size_t)BB * HH;
    size_t idx = (size_t)blockIdx.x * blockDim.x + threadIdx.x;
    if (idx >= CH) return;
    int b = (int)(idx >> 9);
    int h = (int)(idx & 511);

    float ipre = xw[idx]          + hw[idx];
    float gpre = xw[CH + idx]     + hw[CH + idx];
    float opre = xw[2 * CH + idx] + hw[2 * CH + idx];
    float lx   = xw[3 * CH + idx];

    float iv = 1.f / (1.f + expf(-ipre));
    float gv = tanhf(gpre);
    float ov = 1.f / (1.f + expf(-opre));

    int nw = numw[b];
    float sum_e = 0.f, sum_ec = 0.f;
    for (int w = 0; w < nw; w++) {
        size_t e  = ((size_t)(b * WW + w)) * HH + h;
        float pre = lx + edge[e];
        float ie  = 1.f / (1.f + expf(-pre));
        float ex  = expf(ie);
        sum_e  += ex;
        sum_ec += ex * allc[e];
    }

    float ei = expf(iv);
    float c;
    if (nw > 0) {
        float denom = ei + sum_e;
        c = (sum_ec + ei * gv) / denom;
    } else {
        c = gv;   // reference: where(num_word==0, g)
    }
    out[idx]      = ov * tanhf(c);
    out[CH + idx] = c;
}

// ---------------- launch ----------------
extern "C" void kernel_launch(void* const* d_in, const int* in_sizes, int n_in,
                              void* d_out, int out_size)
{
    const float* x    = (const float*)d_in[0];
    const float* h0   = (const float*)d_in[1];
    /* d_in[2] = c0 : unused by reference */
    const float* allc = (const float*)d_in[3];
    const int*   numw = (const int*)  d_in[4];

    const float* w_ii = (const float*)d_in[5];  const float* b_ii = (const float*)d_in[6];
    const float* w_hi = (const float*)d_in[7];  const float* b_hi = (const float*)d_in[8];
    /* 9..12: w_if/b_if/w_hf/b_hf dead in reference */
    const float* w_ig = (const float*)d_in[13]; const float* b_ig = (const float*)d_in[14];
    const float* w_hg = (const float*)d_in[15]; const float* b_hg = (const float*)d_in[16];
    const float* w_io = (const float*)d_in[17]; const float* b_io = (const float*)d_in[18];
    const float* w_ho = (const float*)d_in[19]; const float* b_ho = (const float*)d_in[20];
    const float* w_lx = (const float*)d_in[21]; const float* b_lx = (const float*)d_in[22];
    const float* w_lc = (const float*)d_in[23]; const float* b_lc = (const float*)d_in[24];

    float *xw, *hw, *edge;
    cudaGetSymbolAddress((void**)&xw,   g_xw);
    cudaGetSymbolAddress((void**)&hw,   g_hw);
    cudaGetSymbolAddress((void**)&edge, g_edge);

    const size_t CH = (size_t)BB * HH;

    // x projections: ii, ig, io, lx
    Sets4 sx;
    sx.W[0] = w_ii; sx.bias[0] = b_ii; sx.C[0] = xw;
    sx.W[1] = w_ig; sx.bias[1] = b_ig; sx.C[1] = xw + CH;
    sx.W[2] = w_io; sx.bias[2] = b_io; sx.C[2] = xw + 2 * CH;
    sx.W[3] = w_lx; sx.bias[3] = b_lx; sx.C[3] = xw + 3 * CH;
    sgemm_multi<<<dim3(HH / BN, BB / BM, 4), 256>>>(x, BB, DD, sx);

    // h0 projections: hi, hg, ho
    Sets4 sh;
    sh.W[0] = w_hi; sh.bias[0] = b_hi; sh.C[0] = hw;
    sh.W[1] = w_hg; sh.bias[1] = b_hg; sh.C[1] = hw + CH;
    sh.W[2] = w_ho; sh.bias[2] = b_ho; sh.C[2] = hw + 2 * CH;
    sh.W[3] = w_hi; sh.bias[3] = b_hi; sh.C[3] = hw;   // unused (z<3)
    sgemm_multi<<<dim3(HH / BN, BB / BM, 3), 256>>>(h0, BB, HH, sh);

    // edge GEMM: [B*W, H] @ [H, H] + b_lc
    Sets4 se;
    se.W[0] = w_lc; se.bias[0] = b_lc; se.C[0] = edge;
    se.W[1] = w_lc; se.bias[1] = b_lc; se.C[1] = edge;
    se.W[2] = w_lc; se.bias[2] = b_lc; se.C[2] = edge;
    se.W[3] = w_lc; se.bias[3] = b_lc; se.C[3] = edge;
    sgemm_multi<<<dim3(HH / BN, (BB * WW) / BM, 1), 256>>>(allc, BB * WW, HH, se);

    // fused gates + ragged merge
    int nthreads = 256;
    int nblocks  = (int)((CH + nthreads - 1) / nthreads);
    lattice_epilogue<<<nblocks, nthreads>>>(xw, hw, edge, allc, numw,
                                            (float*)d_out);
}

// round 3
// speedup vs baseline: 4.1195x; 4.1195x over previous
#include <cuda_runtime.h>
#include <cstdint>

// Problem constants
#define BB 8192
#define DD 300
#define HH 512
#define WW 8

// ---------------- scratch (no allocations allowed) ----------------
__device__ float g_xw[(size_t)4 * BB * HH];              // ii, ig, io, lx proj
__device__ float g_hw[(size_t)3 * BB * HH];              // hi, hg, ho proj
__device__ float g_edge[(size_t)BB * WW * HH];           // allc @ w_lc + b_lc
// tf32-rounded copies of GEMM operands
__device__ float g_xr[(size_t)BB * DD];
__device__ float g_h0r[(size_t)BB * HH];
__device__ float g_allcr[(size_t)BB * WW * HH];
__device__ float g_wr[1662976];                          // packed rounded weights

// packed weight offsets (floats)
#define O_II 0
#define O_HI 153600
#define O_IG 415744
#define O_HG 569344
#define O_IO 831488
#define O_HO 985088
#define O_LX 1247232
#define O_LC 1400832

// ---------------- tf32 rounding kernels ----------------
__device__ __forceinline__ float round_tf32(float f) {
    uint32_t o;
    asm("cvt.rna.tf32.f32 %0, %1;" : "=r"(o) : "f"(f));
    return __uint_as_float(o);
}

__global__ void __launch_bounds__(256)
round_kernel(const float* __restrict__ src, float* __restrict__ dst, int n4)
{
    int i = blockIdx.x * blockDim.x + threadIdx.x;
    if (i >= n4) return;
    float4 v = reinterpret_cast<const float4*>(src)[i];
    v.x = round_tf32(v.x); v.y = round_tf32(v.y);
    v.z = round_tf32(v.z); v.w = round_tf32(v.w);
    reinterpret_cast<float4*>(dst)[i] = v;
}

struct RSet { const float* s[8]; int off[8]; int n4[8]; };

__global__ void __launch_bounds__(256)
round_weights(RSet rs, float* __restrict__ dst)
{
    int z = blockIdx.y;
    const float* src = rs.s[z];
    float* d = dst + rs.off[z];
    int n4 = rs.n4[z];
    for (int i = blockIdx.x * blockDim.x + threadIdx.x; i < n4;
         i += gridDim.x * blockDim.x) {
        float4 v = reinterpret_cast<const float4*>(src)[i];
        v.x = round_tf32(v.x); v.y = round_tf32(v.y);
        v.z = round_tf32(v.z); v.w = round_tf32(v.w);
        reinterpret_cast<float4*>(d)[i] = v;
    }
}

// ---------------- tf32 tensor-core SGEMM ----------------
// C_z[M,512] = A[M,K] @ W_z[K,512] + bias_z
struct Sets4 {
    const float* W[4];
    const float* bias[4];
    float*       C[4];
};

#define BM 128
#define BN 128
#define BK 32
#define AS_STRIDE 36    // banks (36g+c)%32 = 4g+c : conflict free
#define BS_STRIDE 136   // banks (136c+g)%32 = 8c+g : conflict free
#define AS_FLOATS (BM * AS_STRIDE)   // 4608
#define BS_FLOATS (BK * BS_STRIDE)   // 4352
#define STAGE_FLOATS (AS_FLOATS + BS_FLOATS)
#define SMEM_BYTES (2 * STAGE_FLOATS * 4)   // 71680

__device__ __forceinline__ void cp16(uint32_t dst, const float* src, bool pred) {
    asm volatile("cp.async.cg.shared.global [%0], [%1], 16, %2;"
                 :: "r"(dst), "l"(src), "r"(pred ? 16 : 0));
}
#define CP_COMMIT() asm volatile("cp.async.commit_group;")
#define CP_WAIT(n)  asm volatile("cp.async.wait_group %0;" :: "n"(n))

__global__ void __launch_bounds__(256, 2)
sgemm_tf32(const float* __restrict__ A, int M, int K, Sets4 sets)
{
    extern __shared__ float sm_[];
    const int z = blockIdx.z;
    const float* __restrict__ W    = sets.W[z];
    const float* __restrict__ bias = sets.bias[z];
    float* __restrict__       C    = sets.C[z];

    const int row0 = blockIdx.y * BM;
    const int col0 = blockIdx.x * BN;

    const int tid  = threadIdx.x;
    const int wid  = tid >> 5;
    const int lane = tid & 31;
    const int wrow = wid >> 1;       // 0..3, 32 rows each
    const int wcol = wid & 1;        // 0..1, 64 cols each
    const int g  = lane >> 2;        // 0..7
    const int c4 = lane & 3;         // 0..3

    float acc[2][8][4];
#pragma unroll
    for (int mt = 0; mt < 2; mt++)
#pragma unroll
        for (int nt = 0; nt < 8; nt++)
#pragma unroll
            for (int r = 0; r < 4; r++) acc[mt][nt][r] = 0.f;

    const int nk = (K + BK - 1) / BK;

    // precompute load indices
    const int a_m  = (tid * 4) >> 5;            // placeholder (recomputed below)
    (void)a_m;

    // stage load
    auto load_stage = [&](int s, int k0) {
        float* As = sm_ + s * STAGE_FLOATS;
        float* Bs = As + AS_FLOATS;
#pragma unroll
        for (int i = 0; i < 4; i++) {
            int id = tid + i * 256;
            int m  = id >> 3;
            int kc = id & 7;
            int gk = k0 + kc * 4;
            bool p = gk < K;
            const float* src = A + (size_t)(row0 + m) * K + (p ? gk : 0);
            uint32_t dst = (uint32_t)__cvta_generic_to_shared(As + m * AS_STRIDE + kc * 4);
            cp16(dst, src, p);
        }
#pragma unroll
        for (int i = 0; i < 4; i++) {
            int id = tid + i * 256;
            int kr = id >> 5;
            int nc = id & 31;
            int gk = k0 + kr;
            bool p = gk < K;
            const float* src = W + (size_t)(p ? gk : 0) * HH + col0 + nc * 4;
            uint32_t dst = (uint32_t)__cvta_generic_to_shared(Bs + kr * BS_STRIDE + nc * 4);
            cp16(dst, src, p);
        }
        CP_COMMIT();
    };

    load_stage(0, 0);

    for (int kb = 0; kb < nk; kb++) {
        if (kb + 1 < nk) {
            load_stage((kb + 1) & 1, (kb + 1) * BK);
            CP_WAIT(1);
        } else {
            CP_WAIT(0);
        }
        __syncthreads();

        const float* As = sm_ + (kb & 1) * STAGE_FLOATS;
        const float* Bs = As + AS_FLOATS;

#pragma unroll
        for (int kk = 0; kk < 4; kk++) {
            uint32_t af[2][4];
            uint32_t bf[8][2];
#pragma unroll
            for (int mt = 0; mt < 2; mt++) {
                const float* p = As + (wrow * 32 + mt * 16 + g) * AS_STRIDE + kk * 8 + c4;
                af[mt][0] = __float_as_uint(p[0]);
                af[mt][1] = __float_as_uint(p[8 * AS_STRIDE]);
                af[mt][2] = __float_as_uint(p[4]);
                af[mt][3] = __float_as_uint(p[8 * AS_STRIDE + 4]);
            }
#pragma unroll
            for (int nt = 0; nt < 8; nt++) {
                const float* q = Bs + (kk * 8 + c4) * BS_STRIDE + wcol * 64 + nt * 8 + g;
                bf[nt][0] = __float_as_uint(q[0]);
                bf[nt][1] = __float_as_uint(q[4 * BS_STRIDE]);
            }
#pragma unroll
            for (int mt = 0; mt < 2; mt++)
#pragma unroll
                for (int nt = 0; nt < 8; nt++) {
                    asm volatile(
                        "mma.sync.aligned.m16n8k8.row.col.f32.tf32.tf32.f32 "
                        "{%0,%1,%2,%3}, {%4,%5,%6,%7}, {%8,%9}, {%0,%1,%2,%3};"
                        : "+f"(acc[mt][nt][0]), "+f"(acc[mt][nt][1]),
                          "+f"(acc[mt][nt][2]), "+f"(acc[mt][nt][3])
                        : "r"(af[mt][0]), "r"(af[mt][1]), "r"(af[mt][2]), "r"(af[mt][3]),
                          "r"(bf[nt][0]), "r"(bf[nt][1]));
                }
        }
        __syncthreads();
    }

    // epilogue: + bias, float2 stores
#pragma unroll
    for (int mt = 0; mt < 2; mt++) {
        int r0 = row0 + wrow * 32 + mt * 16 + g;
#pragma unroll
        for (int nt = 0; nt < 8; nt++) {
            int cc = col0 + wcol * 64 + nt * 8 + c4 * 2;
            float b0 = bias[cc], b1 = bias[cc + 1];
            float2 v0 = make_float2(acc[mt][nt][0] + b0, acc[mt][nt][1] + b1);
            float2 v1 = make_float2(acc[mt][nt][2] + b0, acc[mt][nt][3] + b1);
            *reinterpret_cast<float2*>(&C[(size_t)r0 * HH + cc])       = v0;
            *reinterpret_cast<float2*>(&C[(size_t)(r0 + 8) * HH + cc]) = v1;
        }
    }
}

// ---------------- fused lattice-LSTM epilogue (float4) ----------------
__global__ void __launch_bounds__(256)
lattice_epilogue(const float* __restrict__ xw,   // 4 chunks: ii, ig, io, lx
                 const float* __restrict__ hw,   // 3 chunks: hi, hg, ho
                 const float* __restrict__ edge, // [B*W,H], incl. b_lc
                 const float* __restrict__ allc, // [B,W,H]
                 const int*   __restrict__ numw, // [B]
                 float* __restrict__ out)        // [2*B*H] = h1 then c
{
    const size_t CH  = (size_t)BB * HH;
    const size_t CH4 = CH / 4;
    size_t i4 = (size_t)blockIdx.x * blockDim.x + threadIdx.x;
    if (i4 >= CH4) return;
    int b = (int)(i4 >> 7);            // 128 float4 per row of H=512

    const float4* xw4 = reinterpret_cast<const float4*>(xw);
    const float4* hw4 = reinterpret_cast<const float4*>(hw);

    float4 ipre = xw4[i4];
    float4 hi   = hw4[i4];
    ipre.x += hi.x; ipre.y += hi.y; ipre.z += hi.z; ipre.w += hi.w;
    float4 gpre = xw4[CH4 + i4];
    float4 hg   = hw4[CH4 + i4];
    gpre.x += hg.x; gpre.y += hg.y; gpre.z += hg.z; gpre.w += hg.w;
    float4 opre = xw4[2 * CH4 + i4];
    float4 ho   = hw4[2 * CH4 + i4];
    opre.x += ho.x; opre.y += ho.y; opre.z += ho.z; opre.w += ho.w;
    float4 lx   = xw4[3 * CH4 + i4];

    float iv[4], gv[4], ov[4], lxv[4];
    iv[0] = 1.f / (1.f + expf(-ipre.x)); iv[1] = 1.f / (1.f + expf(-ipre.y));
    iv[2] = 1.f / (1.f + expf(-ipre.z)); iv[3] = 1.f / (1.f + expf(-ipre.w));
    gv[0] = tanhf(gpre.x); gv[1] = tanhf(gpre.y);
    gv[2] = tanhf(gpre.z); gv[3] = tanhf(gpre.w);
    ov[0] = 1.f / (1.f + expf(-opre.x)); ov[1] = 1.f / (1.f + expf(-opre.y));
    ov[2] = 1.f / (1.f + expf(-opre.z)); ov[3] = 1.f / (1.f + expf(-opre.w));
    lxv[0] = lx.x; lxv[1] = lx.y; lxv[2] = lx.z; lxv[3] = lx.w;

    int nw = numw[b];
    float sum_e[4]  = {0.f, 0.f, 0.f, 0.f};
    float sum_ec[4] = {0.f, 0.f, 0.f, 0.f};

    // f4 offset within the b-row: i4 % 128
    size_t h4 = i4 & 127;
    const float4* edge4 = reinterpret_cast<const float4*>(edge);
    const float4* allc4 = reinterpret_cast<const float4*>(allc);

    for (int w = 0; w < nw; w++) {
        size_t e4 = ((size_t)(b * WW + w)) * 128 + h4;
        float4 ed = edge4[e4];
        float4 ac = allc4[e4];
        float pre[4] = {lxv[0] + ed.x, lxv[1] + ed.y, lxv[2] + ed.z, lxv[3] + ed.w};
        float av[4]  = {ac.x, ac.y, ac.z, ac.w};
#pragma unroll
        for (int j = 0; j < 4; j++) {
            float ie = 1.f / (1.f + expf(-pre[j]));
            float ex = expf(ie);
            sum_e[j]  += ex;
            sum_ec[j] += ex * av[j];
        }
    }

    float4 hout, cout;
    float cv[4];
#pragma unroll
    for (int j = 0; j < 4; j++) {
        float ei = expf(iv[j]);
        float c;
        if (nw > 0) c = (sum_ec[j] + ei * gv[j]) / (ei + sum_e[j]);
        else        c = gv[j];
        cv[j] = c;
    }
    hout.x = ov[0] * tanhf(cv[0]); hout.y = ov[1] * tanhf(cv[1]);
    hout.z = ov[2] * tanhf(cv[2]); hout.w = ov[3] * tanhf(cv[3]);
    cout.x = cv[0]; cout.y = cv[1]; cout.z = cv[2]; cout.w = cv[3];

    float4* out4 = reinterpret_cast<float4*>(out);
    out4[i4]       = hout;
    out4[CH4 + i4] = cout;
}

// ---------------- launch ----------------
extern "C" void kernel_launch(void* const* d_in, const int* in_sizes, int n_in,
                              void* d_out, int out_size)
{
    const float* x    = (const float*)d_in[0];
    const float* h0   = (const float*)d_in[1];
    /* d_in[2] = c0 : unused */
    const float* allc = (const float*)d_in[3];
    const int*   numw = (const int*)  d_in[4];

    const float* w_ii = (const float*)d_in[5];  const float* b_ii = (const float*)d_in[6];
    const float* w_hi = (const float*)d_in[7];  const float* b_hi = (const float*)d_in[8];
    /* 9..12: dead */
    const float* w_ig = (const float*)d_in[13]; const float* b_ig = (const float*)d_in[14];
    const float* w_hg = (const float*)d_in[15]; const float* b_hg = (const float*)d_in[16];
    const float* w_io = (const float*)d_in[17]; const float* b_io = (const float*)d_in[18];
    const float* w_ho = (const float*)d_in[19]; const float* b_ho = (const float*)d_in[20];
    const float* w_lx = (const float*)d_in[21]; const float* b_lx = (const float*)d_in[22];
    const float* w_lc = (const float*)d_in[23]; const float* b_lc = (const float*)d_in[24];

    float *xw, *hw, *edge, *xr, *h0r, *allcr, *wr;
    cudaGetSymbolAddress((void**)&xw,    g_xw);
    cudaGetSymbolAddress((void**)&hw,    g_hw);
    cudaGetSymbolAddress((void**)&edge,  g_edge);
    cudaGetSymbolAddress((void**)&xr,    g_xr);
    cudaGetSymbolAddress((void**)&h0r,   g_h0r);
    cudaGetSymbolAddress((void**)&allcr, g_allcr);
    cudaGetSymbolAddress((void**)&wr,    g_wr);

    cudaFuncSetAttribute(sgemm_tf32,
                         cudaFuncAttributeMaxDynamicSharedMemorySize, SMEM_BYTES);

    const size_t CH = (size_t)BB * HH;

    // ---- round inputs to tf32 ----
    {
        int n4 = BB * DD / 4;
        round_kernel<<<(n4 + 255) / 256, 256>>>(x, xr, n4);
        n4 = BB * HH / 4;
        round_kernel<<<(n4 + 255) / 256, 256>>>(h0, h0r, n4);
        n4 = BB * WW * HH / 4;
        round_kernel<<<(n4 + 255) / 256, 256>>>(allc, allcr, n4);

        RSet rs;
        rs.s[0] = w_ii; rs.off[0] = O_II; rs.n4[0] = (DD * HH) / 4;
        rs.s[1] = w_hi; rs.off[1] = O_HI; rs.n4[1] = (HH * HH) / 4;
        rs.s[2] = w_ig; rs.off[2] = O_IG; rs.n4[2] = (DD * HH) / 4;
        rs.s[3] = w_hg; rs.off[3] = O_HG; rs.n4[3] = (HH * HH) / 4;
        rs.s[4] = w_io; rs.off[4] = O_IO; rs.n4[4] = (DD * HH) / 4;
        rs.s[5] = w_ho; rs.off[5] = O_HO; rs.n4[5] = (HH * HH) / 4;
        rs.s[6] = w_lx; rs.off[6] = O_LX; rs.n4[6] = (DD * HH) / 4;
        rs.s[7] = w_lc; rs.off[7] = O_LC; rs.n4[7] = (HH * HH) / 4;
        round_weights<<<dim3(256, 8), 256>>>(rs, wr);
    }

    // ---- GEMMs on tensor pipe ----
    Sets4 sx;
    sx.W[0] = wr + O_II; sx.bias[0] = b_ii; sx.C[0] = xw;
    sx.W[1] = wr + O_IG; sx.bias[1] = b_ig; sx.C[1] = xw + CH;
    sx.W[2] = wr + O_IO; sx.bias[2] = b_io; sx.C[2] = xw + 2 * CH;
    sx.W[3] = wr + O_LX; sx.bias[3] = b_lx; sx.C[3] = xw + 3 * CH;
    sgemm_tf32<<<dim3(HH / BN, BB / BM, 4), 256, SMEM_BYTES>>>(xr, BB, DD, sx);

    Sets4 sh;
    sh.W[0] = wr + O_HI; sh.bias[0] = b_hi; sh.C[0] = hw;
    sh.W[1] = wr + O_HG; sh.bias[1] = b_hg; sh.C[1] = hw + CH;
    sh.W[2] = wr + O_HO; sh.bias[2] = b_ho; sh.C[2] = hw + 2 * CH;
    sh.W[3] = wr + O_HI; sh.bias[3] = b_hi; sh.C[3] = hw;   // unused (z<3)
    sgemm_tf32<<<dim3(HH / BN, BB / BM, 3), 256, SMEM_BYTES>>>(h0r, BB, HH, sh);

    Sets4 se;
    se.W[0] = wr + O_LC; se.bias[0] = b_lc; se.C[0] = edge;
    se.W[1] = se.W[0];   se.bias[1] = b_lc; se.C[1] = edge;
    se.W[2] = se.W[0];   se.bias[2] = b_lc; se.C[2] = edge;
    se.W[3] = se.W[0];   se.bias[3] = b_lc; se.C[3] = edge;
    sgemm_tf32<<<dim3(HH / BN, (BB * WW) / BM, 1), 256, SMEM_BYTES>>>(allcr, BB * WW, HH, se);

    // ---- fused gates + ragged merge ----
    size_t CH4 = CH / 4;
    lattice_epilogue<<<(int)((CH4 + 255) / 256), 256>>>(xw, hw, edge, allc, numw,
                                                        (float*)d_out);
}

// round 4
// speedup vs baseline: 4.7873x; 1.1621x over previous
#include <cuda_runtime.h>
#include <cstdint>

// Problem constants
#define BB 8192
#define DD 300
#define HH 512
#define WW 8

// ---------------- scratch (no allocations allowed) ----------------
__device__ float g_xw[(size_t)4 * BB * HH];              // ii, ig, io, lx proj
__device__ float g_hw[(size_t)3 * BB * HH];              // hi, hg, ho proj
__device__ float g_edge[(size_t)BB * WW * HH];           // allc @ w_lc + b_lc
__device__ float g_wr[1662976];                          // packed tf32-rounded weights

// packed weight offsets (floats)
#define O_II 0
#define O_HI 153600
#define O_IG 415744
#define O_HG 569344
#define O_IO 831488
#define O_HO 985088
#define O_LX 1247232
#define O_LC 1400832

// ---------------- tf32 rounding ----------------
__device__ __forceinline__ float round_tf32(float f) {
    uint32_t o;
    asm("cvt.rna.tf32.f32 %0, %1;" : "=r"(o) : "f"(f));
    return __uint_as_float(o);
}
__device__ __forceinline__ uint32_t cvt_tf32_u(float f) {
    uint32_t o;
    asm("cvt.rna.tf32.f32 %0, %1;" : "=r"(o) : "f"(f));
    return o;
}

struct RSet { const float* s[8]; int off[8]; int n4[8]; };

__global__ void __launch_bounds__(256)
round_weights(RSet rs, float* __restrict__ dst)
{
    int z = blockIdx.y;
    const float* src = rs.s[z];
    float* d = dst + rs.off[z];
    int n4 = rs.n4[z];
    for (int i = blockIdx.x * blockDim.x + threadIdx.x; i < n4;
         i += gridDim.x * blockDim.x) {
        float4 v = reinterpret_cast<const float4*>(src)[i];
        v.x = round_tf32(v.x); v.y = round_tf32(v.y);
        v.z = round_tf32(v.z); v.w = round_tf32(v.w);
        reinterpret_cast<float4*>(d)[i] = v;
    }
}

// ---------------- unified tf32 tensor-core SGEMM ----------------
// 8 jobs in one launch. C_j[M_j,512] = round_tf32(A_j[M_j,K_j]) @ W_j + bias_j
struct Jobs {
    const float* A[8];
    const float* W[8];
    const float* bias[8];
    float*       C[8];
    int          K[8];
    int          start[8];   // first linear block id of job j
};

#define BM 128
#define BN 128
#define BK 32
#define AS_STRIDE 36
#define BS_STRIDE 136
#define AS_FLOATS (BM * AS_STRIDE)
#define BS_FLOATS (BK * BS_STRIDE)
#define STAGE_FLOATS (AS_FLOATS + BS_FLOATS)
#define SMEM_BYTES (2 * STAGE_FLOATS * 4)   // 71680

__device__ __forceinline__ void cp16(uint32_t dst, const float* src, bool pred) {
    asm volatile("cp.async.cg.shared.global [%0], [%1], 16, %2;"
                 :: "r"(dst), "l"(src), "r"(pred ? 16 : 0));
}
#define CP_COMMIT() asm volatile("cp.async.commit_group;")
#define CP_WAIT(n)  asm volatile("cp.async.wait_group %0;" :: "n"(n))

__global__ void __launch_bounds__(256, 2)
sgemm_tf32_multi(Jobs jobs)
{
    extern __shared__ float sm_[];

    // decode job
    const int bid = blockIdx.x;
    int j = 0;
#pragma unroll
    for (int t = 1; t < 8; t++) if (bid >= jobs.start[t]) j = t;

    const float* __restrict__ A    = jobs.A[j];
    const float* __restrict__ W    = jobs.W[j];
    const float* __restrict__ bias = jobs.bias[j];
    float* __restrict__       C    = jobs.C[j];
    const int K = jobs.K[j];

    const int local = bid - jobs.start[j];
    const int row0 = (local >> 2) * BM;   // 4 col-blocks (HH/BN) per row
    const int col0 = (local & 3) * BN;

    const int tid  = threadIdx.x;
    const int wid  = tid >> 5;
    const int lane = tid & 31;
    const int wrow = wid >> 1;       // 0..3, 32 rows each
    const int wcol = wid & 1;        // 0..1, 64 cols each
    const int g  = lane >> 2;        // 0..7
    const int c4 = lane & 3;         // 0..3

    float acc[2][8][4];
#pragma unroll
    for (int mt = 0; mt < 2; mt++)
#pragma unroll
        for (int nt = 0; nt < 8; nt++)
#pragma unroll
            for (int r = 0; r < 4; r++) acc[mt][nt][r] = 0.f;

    const int nk = (K + BK - 1) / BK;

    auto load_stage = [&](int s, int k0) {
        float* As = sm_ + s * STAGE_FLOATS;
        float* Bs = As + AS_FLOATS;
#pragma unroll
        for (int i = 0; i < 4; i++) {
            int id = tid + i * 256;
            int m  = id >> 3;
            int kc = id & 7;
            int gk = k0 + kc * 4;
            bool p = gk < K;
            const float* src = A + (size_t)(row0 + m) * K + (p ? gk : 0);
            uint32_t dst = (uint32_t)__cvta_generic_to_shared(As + m * AS_STRIDE + kc * 4);
            cp16(dst, src, p);
        }
#pragma unroll
        for (int i = 0; i < 4; i++) {
            int id = tid + i * 256;
            int kr = id >> 5;
            int nc = id & 31;
            int gk = k0 + kr;
            bool p = gk < K;
            const float* src = W + (size_t)(p ? gk : 0) * HH + col0 + nc * 4;
            uint32_t dst = (uint32_t)__cvta_generic_to_shared(Bs + kr * BS_STRIDE + nc * 4);
            cp16(dst, src, p);
        }
        CP_COMMIT();
    };

    load_stage(0, 0);

    for (int kb = 0; kb < nk; kb++) {
        if (kb + 1 < nk) {
            load_stage((kb + 1) & 1, (kb + 1) * BK);
            CP_WAIT(1);
        } else {
            CP_WAIT(0);
        }
        __syncthreads();

        const float* As = sm_ + (kb & 1) * STAGE_FLOATS;
        const float* Bs = As + AS_FLOATS;

#pragma unroll
        for (int kk = 0; kk < 4; kk++) {
            uint32_t af[2][4];
            uint32_t bf[8][2];
#pragma unroll
            for (int mt = 0; mt < 2; mt++) {
                const float* p = As + (wrow * 32 + mt * 16 + g) * AS_STRIDE + kk * 8 + c4;
                // A is raw fp32: round to tf32 in-register (weights pre-rounded)
                af[mt][0] = cvt_tf32_u(p[0]);
                af[mt][1] = cvt_tf32_u(p[8 * AS_STRIDE]);
                af[mt][2] = cvt_tf32_u(p[4]);
                af[mt][3] = cvt_tf32_u(p[8 * AS_STRIDE + 4]);
            }
#pragma unroll
            for (int nt = 0; nt < 8; nt++) {
                const float* q = Bs + (kk * 8 + c4) * BS_STRIDE + wcol * 64 + nt * 8 + g;
                bf[nt][0] = __float_as_uint(q[0]);
                bf[nt][1] = __float_as_uint(q[4 * BS_STRIDE]);
            }
#pragma unroll
            for (int mt = 0; mt < 2; mt++)
#pragma unroll
                for (int nt = 0; nt < 8; nt++) {
                    asm volatile(
                        "mma.sync.aligned.m16n8k8.row.col.f32.tf32.tf32.f32 "
                        "{%0,%1,%2,%3}, {%4,%5,%6,%7}, {%8,%9}, {%0,%1,%2,%3};"
                        : "+f"(acc[mt][nt][0]), "+f"(acc[mt][nt][1]),
                          "+f"(acc[mt][nt][2]), "+f"(acc[mt][nt][3])
                        : "r"(af[mt][0]), "r"(af[mt][1]), "r"(af[mt][2]), "r"(af[mt][3]),
                          "r"(bf[nt][0]), "r"(bf[nt][1]));
                }
        }
        __syncthreads();
    }

    // epilogue: + bias, float2 stores
#pragma unroll
    for (int mt = 0; mt < 2; mt++) {
        int r0 = row0 + wrow * 32 + mt * 16 + g;
#pragma unroll
        for (int nt = 0; nt < 8; nt++) {
            int cc = col0 + wcol * 64 + nt * 8 + c4 * 2;
            float b0 = bias[cc], b1 = bias[cc + 1];
            float2 v0 = make_float2(acc[mt][nt][0] + b0, acc[mt][nt][1] + b1);
            float2 v1 = make_float2(acc[mt][nt][2] + b0, acc[mt][nt][3] + b1);
            *reinterpret_cast<float2*>(&C[(size_t)r0 * HH + cc])       = v0;
            *reinterpret_cast<float2*>(&C[(size_t)(r0 + 8) * HH + cc]) = v1;
        }
    }
}

// ---------------- fused lattice-LSTM epilogue (float4) ----------------
__global__ void __launch_bounds__(256)
lattice_epilogue(const float* __restrict__ xw,   // 4 chunks: ii, ig, io, lx
                 const float* __restrict__ hw,   // 3 chunks: hi, hg, ho
                 const float* __restrict__ edge, // [B*W,H], incl. b_lc
                 const float* __restrict__ allc, // [B,W,H]
                 const int*   __restrict__ numw, // [B]
                 float* __restrict__ out)        // [2*B*H] = h1 then c
{
    const size_t CH  = (size_t)BB * HH;
    const size_t CH4 = CH / 4;
    size_t i4 = (size_t)blockIdx.x * blockDim.x + threadIdx.x;
    if (i4 >= CH4) return;
    int b = (int)(i4 >> 7);            // 128 float4 per row of H=512

    const float4* xw4 = reinterpret_cast<const float4*>(xw);
    const float4* hw4 = reinterpret_cast<const float4*>(hw);

    float4 ipre = xw4[i4];
    float4 hi   = hw4[i4];
    ipre.x += hi.x; ipre.y += hi.y; ipre.z += hi.z; ipre.w += hi.w;
    float4 gpre = xw4[CH4 + i4];
    float4 hg   = hw4[CH4 + i4];
    gpre.x += hg.x; gpre.y += hg.y; gpre.z += hg.z; gpre.w += hg.w;
    float4 opre = xw4[2 * CH4 + i4];
    float4 ho   = hw4[2 * CH4 + i4];
    opre.x += ho.x; opre.y += ho.y; opre.z += ho.z; opre.w += ho.w;
    float4 lx   = xw4[3 * CH4 + i4];

    float iv[4], gv[4], ov[4], lxv[4];
    iv[0] = 1.f / (1.f + expf(-ipre.x)); iv[1] = 1.f / (1.f + expf(-ipre.y));
    iv[2] = 1.f / (1.f + expf(-ipre.z)); iv[3] = 1.f / (1.f + expf(-ipre.w));
    gv[0] = tanhf(gpre.x); gv[1] = tanhf(gpre.y);
    gv[2] = tanhf(gpre.z); gv[3] = tanhf(gpre.w);
    ov[0] = 1.f / (1.f + expf(-opre.x)); ov[1] = 1.f / (1.f + expf(-opre.y));
    ov[2] = 1.f / (1.f + expf(-opre.z)); ov[3] = 1.f / (1.f + expf(-opre.w));
    lxv[0] = lx.x; lxv[1] = lx.y; lxv[2] = lx.z; lxv[3] = lx.w;

    int nw = numw[b];
    float sum_e[4]  = {0.f, 0.f, 0.f, 0.f};
    float sum_ec[4] = {0.f, 0.f, 0.f, 0.f};

    size_t h4 = i4 & 127;
    const float4* edge4 = reinterpret_cast<const float4*>(edge);
    const float4* allc4 = reinterpret_cast<const float4*>(allc);

    for (int w = 0; w < nw; w++) {
        size_t e4 = ((size_t)(b * WW + w)) * 128 + h4;
        float4 ed = edge4[e4];
        float4 ac = allc4[e4];
        float pre[4] = {lxv[0] + ed.x, lxv[1] + ed.y, lxv[2] + ed.z, lxv[3] + ed.w};
        float av[4]  = {ac.x, ac.y, ac.z, ac.w};
#pragma unroll
        for (int jj = 0; jj < 4; jj++) {
            float ie = 1.f / (1.f + expf(-pre[jj]));
            float ex = expf(ie);
            sum_e[jj]  += ex;
            sum_ec[jj] += ex * av[jj];
        }
    }

    float4 hout, cout;
    float cv[4];
#pragma unroll
    for (int jj = 0; jj < 4; jj++) {
        float ei = expf(iv[jj]);
        float c;
        if (nw > 0) c = (sum_ec[jj] + ei * gv[jj]) / (ei + sum_e[jj]);
        else        c = gv[jj];
        cv[jj] = c;
    }
    hout.x = ov[0] * tanhf(cv[0]); hout.y = ov[1] * tanhf(cv[1]);
    hout.z = ov[2] * tanhf(cv[2]); hout.w = ov[3] * tanhf(cv[3]);
    cout.x = cv[0]; cout.y = cv[1]; cout.z = cv[2]; cout.w = cv[3];

    float4* out4 = reinterpret_cast<float4*>(out);
    out4[i4]       = hout;
    out4[CH4 + i4] = cout;
}

// ---------------- launch ----------------
extern "C" void kernel_launch(void* const* d_in, const int* in_sizes, int n_in,
                              void* d_out, int out_size)
{
    const float* x    = (const float*)d_in[0];
    const float* h0   = (const float*)d_in[1];
    /* d_in[2] = c0 : unused */
    const float* allc = (const float*)d_in[3];
    const int*   numw = (const int*)  d_in[4];

    const float* w_ii = (const float*)d_in[5];  const float* b_ii = (const float*)d_in[6];
    const float* w_hi = (const float*)d_in[7];  const float* b_hi = (const float*)d_in[8];
    /* 9..12: dead */
    const float* w_ig = (const float*)d_in[13]; const float* b_ig = (const float*)d_in[14];
    const float* w_hg = (const float*)d_in[15]; const float* b_hg = (const float*)d_in[16];
    const float* w_io = (const float*)d_in[17]; const float* b_io = (const float*)d_in[18];
    const float* w_ho = (const float*)d_in[19]; const float* b_ho = (const float*)d_in[20];
    const float* w_lx = (const float*)d_in[21]; const float* b_lx = (const float*)d_in[22];
    const float* w_lc = (const float*)d_in[23]; const float* b_lc = (const float*)d_in[24];

    float *xw, *hw, *edge, *wr;
    cudaGetSymbolAddress((void**)&xw,   g_xw);
    cudaGetSymbolAddress((void**)&hw,   g_hw);
    cudaGetSymbolAddress((void**)&edge, g_edge);
    cudaGetSymbolAddress((void**)&wr,   g_wr);

    cudaFuncSetAttribute(sgemm_tf32_multi,
                         cudaFuncAttributeMaxDynamicSharedMemorySize, SMEM_BYTES);

    const size_t CH = (size_t)BB * HH;

    // ---- round weights to tf32 (small, 6.6 MB total) ----
    {
        RSet rs;
        rs.s[0] = w_ii; rs.off[0] = O_II; rs.n4[0] = (DD * HH) / 4;
        rs.s[1] = w_hi; rs.off[1] = O_HI; rs.n4[1] = (HH * HH) / 4;
        rs.s[2] = w_ig; rs.off[2] = O_IG; rs.n4[2] = (DD * HH) / 4;
        rs.s[3] = w_hg; rs.off[3] = O_HG; rs.n4[3] = (HH * HH) / 4;
        rs.s[4] = w_io; rs.off[4] = O_IO; rs.n4[4] = (DD * HH) / 4;
        rs.s[5] = w_ho; rs.off[5] = O_HO; rs.n4[5] = (HH * HH) / 4;
        rs.s[6] = w_lx; rs.off[6] = O_LX; rs.n4[6] = (DD * HH) / 4;
        rs.s[7] = w_lc; rs.off[7] = O_LC; rs.n4[7] = (HH * HH) / 4;
        round_weights<<<dim3(64, 8), 256>>>(rs, wr);
    }

    // ---- one unified GEMM launch: 8 jobs, 3840 blocks ----
    Jobs jb;
    // x projections (K=300, A=x, 256 blocks each)
    jb.A[0] = x;    jb.W[0] = wr + O_II; jb.bias[0] = b_ii; jb.C[0] = xw;          jb.K[0] = DD; jb.start[0] = 0;
    jb.A[1] = x;    jb.W[1] = wr + O_IG; jb.bias[1] = b_ig; jb.C[1] = xw + CH;     jb.K[1] = DD; jb.start[1] = 256;
    jb.A[2] = x;    jb.W[2] = wr + O_IO; jb.bias[2] = b_io; jb.C[2] = xw + 2 * CH; jb.K[2] = DD; jb.start[2] = 512;
    jb.A[3] = x;    jb.W[3] = wr + O_LX; jb.bias[3] = b_lx; jb.C[3] = xw + 3 * CH; jb.K[3] = DD; jb.start[3] = 768;
    // h projections (K=512, A=h0, 256 blocks each)
    jb.A[4] = h0;   jb.W[4] = wr + O_HI; jb.bias[4] = b_hi; jb.C[4] = hw;          jb.K[4] = HH; jb.start[4] = 1024;
    jb.A[5] = h0;   jb.W[5] = wr + O_HG; jb.bias[5] = b_hg; jb.C[5] = hw + CH;     jb.K[5] = HH; jb.start[5] = 1280;
    jb.A[6] = h0;   jb.W[6] = wr + O_HO; jb.bias[6] = b_ho; jb.C[6] = hw + 2 * CH; jb.K[6] = HH; jb.start[6] = 1536;
    // edge GEMM (K=512, A=allc, M=65536 -> 512 row-blocks * 4 = 2048 blocks)
    jb.A[7] = allc; jb.W[7] = wr + O_LC; jb.bias[7] = b_lc; jb.C[7] = edge;        jb.K[7] = HH; jb.start[7] = 1792;

    sgemm_tf32_multi<<<3840, 256, SMEM_BYTES>>>(jb);

    // ---- fused gates + ragged merge ----
    size_t CH4 = CH / 4;
    lattice_epilogue<<<(int)((CH4 + 255) / 256), 256>>>(xw, hw, edge, allc, numw,
                                                        (float*)d_out);
}

// round 8
// speedup vs baseline: 6.6955x; 1.3986x over previous
#include <cuda_runtime.h>
#include <cuda_fp16.h>
#include <cstdint>

// Problem constants
#define BB 8192
#define DD 300
#define HH 512
#define WW 8
#define KC 832          // combined K: 320 (x, padded from 300) + 512 (h0)
#define KXP 320         // padded x-only K

// ---------------- scratch (no allocations allowed) ----------------
// fp16 packed activations [B, 832]: cols 0..299 = x, 300..319 = 0 (.bss), 320..831 = h0
__device__ __half g_xh[(size_t)BB * KC];
// fp16 allc [B*W, 512]
__device__ __half g_ac16[(size_t)BB * WW * HH];
// fp16 weights, transposed to [N=512, Kpad]; pads zero via .bss
__device__ __half g_wt16[1703936];
#define G_I  0          // gate i:  [512,832]  (w_ii | w_hi)
#define G_G  425984     // gate g:  [512,832]
#define G_O  851968     // gate o:  [512,832]
#define G_LX 1277952    // lx:      [512,320]
#define G_LC 1441792    // lc:      [512,512]
// fp32 GEMM outputs: 4 chunks [B,H]: ipre, gpre, opre, lxproj
__device__ float g_pre[(size_t)4 * BB * HH];
// fp32 edge output [B*W, H]
__device__ float g_edge[(size_t)BB * WW * HH];
// combined biases: b_ii+b_hi, b_ig+b_hg, b_io+b_ho
__device__ float g_bsum[3 * HH];

// ---------------- helpers ----------------
__device__ __forceinline__ uint32_t smem_u32(const void* p) {
    uint32_t a;
    asm("{ .reg .u64 t; cvta.to.shared.u64 t, %1; cvt.u32.u64 %0, t; }"
        : "=r"(a) : "l"(p));
    return a;
}
__device__ __forceinline__ void cp16(uint32_t dst, const void* src, bool pred) {
    asm volatile("cp.async.cg.shared.global [%0], [%1], 16, %2;"
                 :: "r"(dst), "l"(src), "r"(pred ? 16 : 0));
}
#define CP_COMMIT() asm volatile("cp.async.commit_group;")
#define CP_WAIT(n)  asm volatile("cp.async.wait_group %0;" :: "n"(n))

// ---------------- conversion kernels ----------------
__global__ void __launch_bounds__(256)
conv_pack(const float* __restrict__ src, __half* __restrict__ dst,
          int f4_per_row, int src_stride, int dst_stride, int dst_off, int n4)
{
    int i = blockIdx.x * blockDim.x + threadIdx.x;
    if (i >= n4) return;
    int row = i / f4_per_row, c = i - row * f4_per_row;
    float4 v = *reinterpret_cast<const float4*>(src + (size_t)row * src_stride + c * 4);
    __half2 h01 = __floats2half2_rn(v.x, v.y);
    __half2 h23 = __floats2half2_rn(v.z, v.w);
    uint2 o = make_uint2(*reinterpret_cast<uint32_t*>(&h01),
                         *reinterpret_cast<uint32_t*>(&h23));
    *reinterpret_cast<uint2*>(dst + (size_t)row * dst_stride + dst_off + c * 4) = o;
}

struct TSet { const float* s[8]; int K[8]; int dst[8]; int strideW[8]; };

// transpose + convert: w[K,512] fp32 -> wt16[n][dstoff + k] fp16
__global__ void __launch_bounds__(256)
prep_w(TSet ts, __half* __restrict__ wt)
{
    int z = blockIdx.z;
    int K = ts.K[z];
    int k0 = blockIdx.y * 32;
    if (k0 >= K) return;
    int n0 = blockIdx.x * 32;

    __shared__ float s[32][33];
    int tx = threadIdx.x & 31, ty = threadIdx.x >> 5;   // ty 0..7
#pragma unroll
    for (int i = 0; i < 4; i++) {
        int k = k0 + ty + 8 * i;
        s[ty + 8 * i][tx] = (k < K) ? ts.s[z][(size_t)k * HH + n0 + tx] : 0.f;
    }
    __syncthreads();
#pragma unroll
    for (int i = 0; i < 4; i++) {
        int n = n0 + ty + 8 * i;
        int kk = k0 + tx;
        if (kk < K)
            wt[(size_t)ts.dst[z] + (size_t)n * ts.strideW[z] + kk] =
                __float2half_rn(s[tx][ty + 8 * i]);
    }
}

__global__ void __launch_bounds__(256)
bias_sum(const float* a0, const float* b0, const float* a1, const float* b1,
         const float* a2, const float* b2, float* out)
{
    int i = blockIdx.x * blockDim.x + threadIdx.x;
    if (i >= HH) return;
    out[i]          = a0[i] + b0[i];
    out[HH + i]     = a1[i] + b1[i];
    out[2 * HH + i] = a2[i] + b2[i];
}

// ---------------- fp16 tensor-core GEMM, 5 jobs, one launch ----------------
// C_j[M,512] = A_j[M,K] (fp16) @ W_j[K,512] (fp16, stored [N,K]) + bias_j
struct Jobs5 {
    const __half* A[5];
    const __half* W[5];
    const float*  bias[5];
    float*        C[5];
    int           sA[5];    // A row stride (halves)
    int           sW[5];    // W row stride (halves)
    int           nk[5];    // K / 64
    int           start[5];
};

#define BKH 64              // K-depth per mainloop iter (halves) = 128 bytes/row
#define ROWB 144            // smem row pitch bytes (72 halves, conflict-free)
#define TILE_B (128 * ROWB) // 18432
#define STAGE_B (2 * TILE_B)
#define SMEM_BYTES (2 * STAGE_B)   // 73728

__global__ void __launch_bounds__(256)
gemm_fp16(Jobs5 jb)
{
    extern __shared__ __align__(16) char sm_[];

    const int bid = blockIdx.x;
    int j = 0;
#pragma unroll
    for (int t = 1; t < 5; t++) if (bid >= jb.start[t]) j = t;

    const __half* __restrict__ A    = jb.A[j];
    const __half* __restrict__ W    = jb.W[j];
    const float*  __restrict__ bias = jb.bias[j];
    float*        __restrict__ C    = jb.C[j];
    const int sA = jb.sA[j], sW = jb.sW[j], nk = jb.nk[j];

    const int local = bid - jb.start[j];
    const int row0 = (local >> 2) * 128;
    const int col0 = (local & 3) * 128;

    const int tid  = threadIdx.x;
    const int wid  = tid >> 5;
    const int lane = tid & 31;
    const int wrow = wid >> 1;     // 0..3 (32 rows each)
    const int wcol = wid & 1;      // 0..1 (64 cols each)
    const int g  = lane >> 2;
    const int c4 = lane & 3;

    float acc[2][8][4];
#pragma unroll
    for (int mt = 0; mt < 2; mt++)
#pragma unroll
        for (int nt = 0; nt < 8; nt++)
#pragma unroll
            for (int r = 0; r < 4; r++) acc[mt][nt][r] = 0.f;

    auto load_stage = [&](int s, int kb) {
        uint32_t sAb = smem_u32(sm_) + s * STAGE_B;
        uint32_t sBb = sAb + TILE_B;
        int k0 = kb * BKH;
#pragma unroll
        for (int i = 0; i < 4; i++) {
            int id = tid + i * 256;
            int r = id >> 3, ch = id & 7;
            cp16(sAb + r * ROWB + ch * 16,
                 A + (size_t)(row0 + r) * sA + k0 + ch * 8, true);
        }
#pragma unroll
        for (int i = 0; i < 4; i++) {
            int id = tid + i * 256;
            int r = id >> 3, ch = id & 7;
            cp16(sBb + r * ROWB + ch * 16,
                 W + (size_t)(col0 + r) * sW + k0 + ch * 8, true);
        }
        CP_COMMIT();
    };

    load_stage(0, 0);

    for (int kb = 0; kb < nk; kb++) {
        if (kb + 1 < nk) {
            load_stage((kb + 1) & 1, kb + 1);
            CP_WAIT(1);
        } else {
            CP_WAIT(0);
        }
        __syncthreads();

        const char* As = sm_ + (kb & 1) * STAGE_B;
        const char* Bs = As + TILE_B;

#pragma unroll
        for (int kk = 0; kk < 4; kk++) {
            uint32_t af[2][4], bf[8][2];
            const int kby = (kk * 16 + 2 * c4) * 2;   // byte offset of k-pair
#pragma unroll
            for (int mt = 0; mt < 2; mt++) {
                const char* p = As + (wrow * 32 + mt * 16 + g) * ROWB + kby;
                af[mt][0] = *reinterpret_cast<const uint32_t*>(p);
                af[mt][1] = *reinterpret_cast<const uint32_t*>(p + 8 * ROWB);
                af[mt][2] = *reinterpret_cast<const uint32_t*>(p + 16);
                af[mt][3] = *reinterpret_cast<const uint32_t*>(p + 8 * ROWB + 16);
            }
#pragma unroll
            for (int nt = 0; nt < 8; nt++) {
                const char* q = Bs + (wcol * 64 + nt * 8 + g) * ROWB + kby;
                bf[nt][0] = *reinterpret_cast<const uint32_t*>(q);
                bf[nt][1] = *reinterpret_cast<const uint32_t*>(q + 16);
            }
#pragma unroll
            for (int mt = 0; mt < 2; mt++)
#pragma unroll
                for (int nt = 0; nt < 8; nt++) {
                    asm volatile(
                        "mma.sync.aligned.m16n8k16.row.col.f32.f16.f16.f32 "
                        "{%0,%1,%2,%3}, {%4,%5,%6,%7}, {%8,%9}, {%0,%1,%2,%3};"
                        : "+f"(acc[mt][nt][0]), "+f"(acc[mt][nt][1]),
                          "+f"(acc[mt][nt][2]), "+f"(acc[mt][nt][3])
                        : "r"(af[mt][0]), "r"(af[mt][1]), "r"(af[mt][2]), "r"(af[mt][3]),
                          "r"(bf[nt][0]), "r"(bf[nt][1]));
                }
        }
        __syncthreads();
    }

    // epilogue: + bias, float2 stores (c0,c1 at row g; c2,c3 at row g+8)
#pragma unroll
    for (int mt = 0; mt < 2; mt++) {
        int r0 = row0 + wrow * 32 + mt * 16 + g;
#pragma unroll
        for (int nt = 0; nt < 8; nt++) {
            int cc = col0 + wcol * 64 + nt * 8 + c4 * 2;
            float b0 = bias[cc], b1 = bias[cc + 1];
            float2 v0 = make_float2(acc[mt][nt][0] + b0, acc[mt][nt][1] + b1);
            float2 v1 = make_float2(acc[mt][nt][2] + b0, acc[mt][nt][3] + b1);
            *reinterpret_cast<float2*>(&C[(size_t)r0 * HH + cc])       = v0;
            *reinterpret_cast<float2*>(&C[(size_t)(r0 + 8) * HH + cc]) = v1;
        }
    }
}

// ---------------- fused lattice-LSTM epilogue (float4) ----------------
__global__ void __launch_bounds__(256)
lattice_epilogue(const float* __restrict__ pre,  // 4 chunks: ipre,gpre,opre,lx
                 const float* __restrict__ edge, // [B*W,H], incl. b_lc
                 const float* __restrict__ allc, // [B,W,H] fp32 original
                 const int*   __restrict__ numw,
                 float* __restrict__ out)        // [2*B*H] = h1 then c
{
    const size_t CH4 = (size_t)BB * HH / 4;
    size_t i4 = (size_t)blockIdx.x * blockDim.x + threadIdx.x;
    if (i4 >= CH4) return;
    int b = (int)(i4 >> 7);

    const float4* pre4 = reinterpret_cast<const float4*>(pre);
    float4 ipre = pre4[i4];
    float4 gpre = pre4[CH4 + i4];
    float4 opre = pre4[2 * CH4 + i4];
    float4 lx   = pre4[3 * CH4 + i4];

    float iv[4], gv[4], ov[4], lxv[4];
    iv[0] = 1.f / (1.f + expf(-ipre.x)); iv[1] = 1.f / (1.f + expf(-ipre.y));
    iv[2] = 1.f / (1.f + expf(-ipre.z)); iv[3] = 1.f / (1.f + expf(-ipre.w));
    gv[0] = tanhf(gpre.x); gv[1] = tanhf(gpre.y);
    gv[2] = tanhf(gpre.z); gv[3] = tanhf(gpre.w);
    ov[0] = 1.f / (1.f + expf(-opre.x)); ov[1] = 1.f / (1.f + expf(-opre.y));
    ov[2] = 1.f / (1.f + expf(-opre.z)); ov[3] = 1.f / (1.f + expf(-opre.w));
    lxv[0] = lx.x; lxv[1] = lx.y; lxv[2] = lx.z; lxv[3] = lx.w;

    int nw = numw[b];
    float sum_e[4]  = {0.f, 0.f, 0.f, 0.f};
    float sum_ec[4] = {0.f, 0.f, 0.f, 0.f};

    size_t h4 = i4 & 127;
    const float4* edge4 = reinterpret_cast<const float4*>(edge);
    const float4* allc4 = reinterpret_cast<const float4*>(allc);

    for (int w = 0; w < nw; w++) {
        size_t e4 = ((size_t)(b * WW + w)) * 128 + h4;
        float4 ed = edge4[e4];
        float4 ac = allc4[e4];
        float prev[4] = {lxv[0] + ed.x, lxv[1] + ed.y, lxv[2] + ed.z, lxv[3] + ed.w};
        float av[4]   = {ac.x, ac.y, ac.z, ac.w};
#pragma unroll
        for (int jj = 0; jj < 4; jj++) {
            float ie = 1.f / (1.f + expf(-prev[jj]));
            float ex = expf(ie);
            sum_e[jj]  += ex;
            sum_ec[jj] += ex * av[jj];
        }
    }

    float4 hout, cout;
    float cv[4];
#pragma unroll
    for (int jj = 0; jj < 4; jj++) {
        float ei = expf(iv[jj]);
        float c;
        if (nw > 0) c = (sum_ec[jj] + ei * gv[jj]) / (ei + sum_e[jj]);
        else        c = gv[jj];
        cv[jj] = c;
    }
    hout.x = ov[0] * tanhf(cv[0]); hout.y = ov[1] * tanhf(cv[1]);
    hout.z = ov[2] * tanhf(cv[2]); hout.w = ov[3] * tanhf(cv[3]);
    cout.x = cv[0]; cout.y = cv[1]; cout.z = cv[2]; cout.w = cv[3];

    float4* out4 = reinterpret_cast<float4*>(out);
    out4[i4]       = hout;
    out4[CH4 + i4] = cout;
}

// ---------------- launch ----------------
extern "C" void kernel_launch(void* const* d_in, const int* in_sizes, int n_in,
                              void* d_out, int out_size)
{
    const float* x    = (const float*)d_in[0];
    const float* h0   = (const float*)d_in[1];
    /* d_in[2] = c0 : unused */
    const float* allc = (const float*)d_in[3];
    const int*   numw = (const int*)  d_in[4];

    const float* w_ii = (const float*)d_in[5];  const float* b_ii = (const float*)d_in[6];
    const float* w_hi = (const float*)d_in[7];  const float* b_hi = (const float*)d_in[8];
    /* 9..12: dead */
    const float* w_ig = (const float*)d_in[13]; const float* b_ig = (const float*)d_in[14];
    const float* w_hg = (const float*)d_in[15]; const float* b_hg = (const float*)d_in[16];
    const float* w_io = (const float*)d_in[17]; const float* b_io = (const float*)d_in[18];
    const float* w_ho = (const float*)d_in[19]; const float* b_ho = (const float*)d_in[20];
    const float* w_lx = (const float*)d_in[21]; const float* b_lx = (const float*)d_in[22];
    const float* w_lc = (const float*)d_in[23]; const float* b_lc = (const float*)d_in[24];

    __half *xh, *ac16, *wt16;
    float *pre, *edge, *bsum;
    cudaGetSymbolAddress((void**)&xh,   g_xh);
    cudaGetSymbolAddress((void**)&ac16, g_ac16);
    cudaGetSymbolAddress((void**)&wt16, g_wt16);
    cudaGetSymbolAddress((void**)&pre,  g_pre);
    cudaGetSymbolAddress((void**)&edge, g_edge);
    cudaGetSymbolAddress((void**)&bsum, g_bsum);

    cudaFuncSetAttribute(gemm_fp16,
                         cudaFuncAttributeMaxDynamicSharedMemorySize, SMEM_BYTES);

    const size_t CH = (size_t)BB * HH;

    // ---- convert activations to fp16 (packed [x | h0]) ----
    {
        int n4 = BB * (DD / 4);             // 300/4 = 75 float4 per row
        conv_pack<<<(n4 + 255) / 256, 256>>>(x, xh, DD / 4, DD, KC, 0, n4);
        n4 = BB * (HH / 4);
        conv_pack<<<(n4 + 255) / 256, 256>>>(h0, xh, HH / 4, HH, KC, KXP, n4);
        n4 = BB * WW * (HH / 4);
        conv_pack<<<(n4 + 255) / 256, 256>>>(allc, ac16, HH / 4, HH, HH, 0, n4);
    }
    // ---- weights: round/convert + transpose into [N,Kpad] fp16 ----
    {
        TSet ts;
        ts.s[0] = w_ii; ts.K[0] = DD; ts.dst[0] = G_I;        ts.strideW[0] = KC;
        ts.s[1] = w_hi; ts.K[1] = HH; ts.dst[1] = G_I + KXP;  ts.strideW[1] = KC;
        ts.s[2] = w_ig; ts.K[2] = DD; ts.dst[2] = G_G;        ts.strideW[2] = KC;
        ts.s[3] = w_hg; ts.K[3] = HH; ts.dst[3] = G_G + KXP;  ts.strideW[3] = KC;
        ts.s[4] = w_io; ts.K[4] = DD; ts.dst[4] = G_O;        ts.strideW[4] = KC;
        ts.s[5] = w_ho; ts.K[5] = HH; ts.dst[5] = G_O + KXP;  ts.strideW[5] = KC;
        ts.s[6] = w_lx; ts.K[6] = DD; ts.dst[6] = G_LX;       ts.strideW[6] = KXP;
        ts.s[7] = w_lc; ts.K[7] = HH; ts.dst[7] = G_LC;       ts.strideW[7] = HH;
        prep_w<<<dim3(16, 16, 8), 256>>>(ts, wt16);
        bias_sum<<<2, 256>>>(b_ii, b_hi, b_ig, b_hg, b_io, b_ho, bsum);
    }

    // ---- one fp16 GEMM launch: 5 jobs, 3072 CTAs ----
    Jobs5 jb;
    // gates i/g/o: A = [x|h0], K = 832
    jb.A[0] = xh;   jb.W[0] = wt16 + G_I;  jb.bias[0] = bsum;          jb.C[0] = pre;          jb.sA[0] = KC; jb.sW[0] = KC;  jb.nk[0] = KC / BKH;  jb.start[0] = 0;
    jb.A[1] = xh;   jb.W[1] = wt16 + G_G;  jb.bias[1] = bsum + HH;     jb.C[1] = pre + CH;     jb.sA[1] = KC; jb.sW[1] = KC;  jb.nk[1] = KC / BKH;  jb.start[1] = 256;
    jb.A[2] = xh;   jb.W[2] = wt16 + G_O;  jb.bias[2] = bsum + 2 * HH; jb.C[2] = pre + 2 * CH; jb.sA[2] = KC; jb.sW[2] = KC;  jb.nk[2] = KC / BKH;  jb.start[2] = 512;
    // lx: A = same packed buffer, first 320 cols only
    jb.A[3] = xh;   jb.W[3] = wt16 + G_LX; jb.bias[3] = b_lx;          jb.C[3] = pre + 3 * CH; jb.sA[3] = KC; jb.sW[3] = KXP; jb.nk[3] = KXP / BKH; jb.start[3] = 768;
    // edge: allc fp16, M = 65536
    jb.A[4] = ac16; jb.W[4] = wt16 + G_LC; jb.bias[4] = b_lc;          jb.C[4] = edge;         jb.sA[4] = HH; jb.sW[4] = HH;  jb.nk[4] = HH / BKH;  jb.start[4] = 1024;

    gemm_fp16<<<3072, 256, SMEM_BYTES>>>(jb);

    // ---- fused gates + ragged merge ----
    size_t CH4 = CH / 4;
    lattice_epilogue<<<(int)((CH4 + 255) / 256), 256>>>(pre, edge, allc, numw,
                                                        (float*)d_out);
}